// round 14
// baseline (speedup 1.0000x reference)
#include <cuda_runtime.h>
#include <cuda_bf16.h>

#define IN_DIM 128
#define OUT_DIM 64
#define N_MAX 100000
#define E_MAX 1600000
#define NEG_SLOPE 0.2f

// ---------------- scratch (static device globals: allocation-free) ----------
__device__ float d_h[(size_t)N_MAX * OUT_DIM];   // transformed features
__device__ float d_as[N_MAX];                    // h @ att_src
__device__ float d_ad[N_MAX];                    // h @ att_dst
__device__ int   d_deg[N_MAX];                   // in-degree histogram
__device__ int   d_excl[N_MAX];                  // tile-local exclusive prefix
__device__ int   d_bsum[128];                    // per-tile totals
__device__ int   d_start[N_MAX + 1];             // CSR row offsets (by dst)
__device__ int   d_cursor[N_MAX];                // placement cursors
__device__ int2  d_rec[E_MAX];                   // bucketed (src, w-as-bits)
__device__ int   d_is64;                         // edge_index dtype flag

__device__ __forceinline__ float lrelu(float v) {
    return v > 0.f ? v : NEG_SLOPE * v;
}

// ---------------- K0: detect edge_index element width ------------------------
__global__ void k0_detect(const long long* __restrict__ ei, int N)
{
    int ok64 = 1;
    for (int i = 0; i < 64; i++) {
        long long v = ei[i];
        if (v < 0 || v >= (long long)N) { ok64 = 0; break; }
    }
    d_is64 = ok64;
}

// ---------------- K2a: dst-degree histogram ----------------------------------
__global__ __launch_bounds__(256) void k2a_hist(
    const void* __restrict__ ei_raw, int E, int N)
{
    int i = blockIdx.x * blockDim.x + threadIdx.x;
    if (i >= E) return;
    int d;
    if (d_is64) {
        d = (int)((const long long*)ei_raw)[(size_t)E + i];
    } else {
        d = ((const int*)ei_raw)[(size_t)E + i];
    }
    if ((unsigned)d >= (unsigned)N) d = 0;
    atomicAdd(&d_deg[d], 1);
}

// ---------------- kS1: per-tile scan ------------------------------------------
__global__ __launch_bounds__(1024) void kS1_tile_scan(int N)
{
    __shared__ int sh[1024];
    int t = threadIdx.x;
    int gi = blockIdx.x * 1024 + t;
    int v = (gi < N) ? d_deg[gi] : 0;
    sh[t] = v;
    __syncthreads();
#pragma unroll
    for (int off = 1; off < 1024; off <<= 1) {
        int u = (t >= off) ? sh[t - off] : 0;
        __syncthreads();
        sh[t] += u;
        __syncthreads();
    }
    if (gi < N) d_excl[gi] = sh[t] - v;
    if (t == 1023) d_bsum[blockIdx.x] = sh[t];
}

// ---------------- K1: 4x8 register-tile GEMM, double-buffered x ---------------
// 256 threads: rg = t>>3 (32 groups x 4 rows = 128 rows/block), cg = t&7
// (8 groups x 8 cols). Pure GEMM: attention epilogue moved to kA.
__global__ __launch_bounds__(256) void k1_gemm(
    const float* __restrict__ x, const float* __restrict__ W, int N)
{
    __shared__ float Wc[IN_DIM * OUT_DIM];   // 32 KB, [k][c] row-major

    int t = threadIdx.x;
    {
        const float4* Wg = reinterpret_cast<const float4*>(W);
        float4* Ws = reinterpret_cast<float4*>(Wc);
        for (int i = t; i < IN_DIM * OUT_DIM / 4; i += 256) Ws[i] = Wg[i];
    }
    __syncthreads();

    int cg = t & 7;
    int rg = t >> 3;
    int row0 = blockIdx.x * 128 + rg * 4;

    float4 acc[4][2];
#pragma unroll
    for (int r = 0; r < 4; r++) {
        acc[r][0] = make_float4(0.f, 0.f, 0.f, 0.f);
        acc[r][1] = make_float4(0.f, 0.f, 0.f, 0.f);
    }

    const float4* x4  = reinterpret_cast<const float4*>(x);
    const float4* Wc4 = reinterpret_cast<const float4*>(Wc);

    float4 xcur[4], xnxt[4];
#pragma unroll
    for (int r = 0; r < 4; r++) {
        int gr = row0 + r;
        xcur[r] = (gr < N) ? x4[(size_t)gr * 32] : make_float4(0.f, 0.f, 0.f, 0.f);
    }

    for (int kq = 0; kq < 32; kq++) {
        if (kq < 31) {
#pragma unroll
            for (int r = 0; r < 4; r++) {
                int gr = row0 + r;
                xnxt[r] = (gr < N) ? x4[(size_t)gr * 32 + kq + 1]
                                   : make_float4(0.f, 0.f, 0.f, 0.f);
            }
        }
#pragma unroll
        for (int kk = 0; kk < 4; kk++) {
            int k = kq * 4 + kk;
            float4 w0 = Wc4[k * 16 + cg * 2];
            float4 w1 = Wc4[k * 16 + cg * 2 + 1];
#pragma unroll
            for (int r = 0; r < 4; r++) {
                float xv = (kk == 0) ? xcur[r].x : (kk == 1) ? xcur[r].y
                         : (kk == 2) ? xcur[r].z : xcur[r].w;
                acc[r][0].x = fmaf(xv, w0.x, acc[r][0].x);
                acc[r][0].y = fmaf(xv, w0.y, acc[r][0].y);
                acc[r][0].z = fmaf(xv, w0.z, acc[r][0].z);
                acc[r][0].w = fmaf(xv, w0.w, acc[r][0].w);
                acc[r][1].x = fmaf(xv, w1.x, acc[r][1].x);
                acc[r][1].y = fmaf(xv, w1.y, acc[r][1].y);
                acc[r][1].z = fmaf(xv, w1.z, acc[r][1].z);
                acc[r][1].w = fmaf(xv, w1.w, acc[r][1].w);
            }
        }
#pragma unroll
        for (int r = 0; r < 4; r++) xcur[r] = xnxt[r];
    }

    float4* h4 = reinterpret_cast<float4*>(d_h);
#pragma unroll
    for (int r = 0; r < 4; r++) {
        int gr = row0 + r;
        if (gr < N) {
            h4[(size_t)gr * 16 + cg * 2]     = acc[r][0];
            h4[(size_t)gr * 16 + cg * 2 + 1] = acc[r][1];
        }
    }
}

// ---------------- kA: attention dots a_s = h@att_src, a_d = h@att_dst --------
// Thread per node: 16 LDG.128 over L2-resident h.
__global__ __launch_bounds__(256) void kA_dots(
    const float* __restrict__ att_src, const float* __restrict__ att_dst, int N)
{
    int n = blockIdx.x * blockDim.x + threadIdx.x;
    if (n >= N) return;
    const float4* h4 = reinterpret_cast<const float4*>(d_h) + (size_t)n * 16;
    const float4* As = reinterpret_cast<const float4*>(att_src);
    const float4* Ad = reinterpret_cast<const float4*>(att_dst);
    float ps = 0.f, pd = 0.f;
#pragma unroll
    for (int i = 0; i < 16; i++) {
        float4 hv = h4[i];
        float4 a = As[i];
        float4 b = Ad[i];
        ps += hv.x * a.x + hv.y * a.y + hv.z * a.z + hv.w * a.w;
        pd += hv.x * b.x + hv.y * b.y + hv.z * b.z + hv.w * b.w;
    }
    d_as[n] = ps;
    d_ad[n] = pd;
}

// ---------------- kS23: finalize offsets + zero histogram --------------------
__global__ __launch_bounds__(256) void kS23_finalize(int N, int E, int nTiles)
{
    __shared__ int sh[128];
    int t = threadIdx.x;
    if (t < 128) sh[t] = (t < nTiles) ? d_bsum[t] : 0;
    __syncthreads();
    if (t == 0) {
        int run = 0;
        for (int i = 0; i < nTiles; i++) {
            int v = sh[i];
            sh[i] = run;
            run += v;
        }
    }
    __syncthreads();

    int i = blockIdx.x * blockDim.x + t;
    if (i < N) {
        int s = d_excl[i] + sh[i >> 10];
        d_start[i]  = s;
        d_cursor[i] = s;
        d_deg[i]    = 0;
    }
    if (i == 0) d_start[N] = E;
}

// ---------------- K2c: decode + weight + place --------------------------------
__global__ __launch_bounds__(256) void k2c_place(
    const void* __restrict__ ei_raw, int E, int N)
{
    int i = blockIdx.x * blockDim.x + threadIdx.x;
    if (i >= E) return;
    int s, d;
    if (d_is64) {
        const long long* p = (const long long*)ei_raw;
        s = (int)p[i];
        d = (int)p[(size_t)E + i];
    } else {
        const int* p = (const int*)ei_raw;
        s = p[i];
        d = p[(size_t)E + i];
    }
    if ((unsigned)s >= (unsigned)N) s = 0;
    if ((unsigned)d >= (unsigned)N) d = 0;

    float w = __expf(lrelu(d_as[s] + d_ad[d]));
    int p = atomicAdd(&d_cursor[d], 1);
    d_rec[p] = make_int2(s, __float_as_int(w));
}

// ---------------- K5: gather-aggregate, half-warp float4 ---------------------
__global__ __launch_bounds__(256) void k5_gather(
    float4* __restrict__ out, const float* __restrict__ bias, int N)
{
    int t = threadIdx.x;
    int warp = t >> 5, lane = t & 31;
    int half = lane >> 4;
    int hl   = lane & 15;
    int n = blockIdx.x * 8 + warp;
    if (n >= N) return;

    const float4* h4 = reinterpret_cast<const float4*>(d_h);

    float wself = __expf(lrelu(d_as[n] + d_ad[n]));
    float4 hv = h4[(size_t)n * 16 + hl];
    float4 acc;
    float wsum;
    if (half == 0) {
        acc = make_float4(wself * hv.x, wself * hv.y, wself * hv.z, wself * hv.w);
        wsum = wself;
    } else {
        acc = make_float4(0.f, 0.f, 0.f, 0.f);
        wsum = 0.f;
    }

    int beg = d_start[n], end = d_start[n + 1];
    int j = beg;
    for (; j + 4 <= end; j += 4) {
        int2 rA = d_rec[j + half];
        int2 rB = d_rec[j + 2 + half];
        float4 vA = h4[(size_t)rA.x * 16 + hl];
        float4 vB = h4[(size_t)rB.x * 16 + hl];
        float wA = __int_as_float(rA.y);
        float wB = __int_as_float(rB.y);
        acc.x = fmaf(wA, vA.x, acc.x); acc.y = fmaf(wA, vA.y, acc.y);
        acc.z = fmaf(wA, vA.z, acc.z); acc.w = fmaf(wA, vA.w, acc.w);
        acc.x = fmaf(wB, vB.x, acc.x); acc.y = fmaf(wB, vB.y, acc.y);
        acc.z = fmaf(wB, vB.z, acc.z); acc.w = fmaf(wB, vB.w, acc.w);
        wsum += wA + wB;
    }
    if (j + 2 <= end) {
        int2 r = d_rec[j + half];
        float4 v = h4[(size_t)r.x * 16 + hl];
        float w = __int_as_float(r.y);
        acc.x = fmaf(w, v.x, acc.x); acc.y = fmaf(w, v.y, acc.y);
        acc.z = fmaf(w, v.z, acc.z); acc.w = fmaf(w, v.w, acc.w);
        wsum += w;
        j += 2;
    }
    if (j < end) {
        int2 r = d_rec[j];
        float w = (half == 0) ? __int_as_float(r.y) : 0.f;
        float4 v = h4[(size_t)r.x * 16 + hl];
        acc.x = fmaf(w, v.x, acc.x); acc.y = fmaf(w, v.y, acc.y);
        acc.z = fmaf(w, v.z, acc.z); acc.w = fmaf(w, v.w, acc.w);
        wsum += w;
    }

    wsum  += __shfl_xor_sync(0xffffffffu, wsum,  16);
    acc.x += __shfl_xor_sync(0xffffffffu, acc.x, 16);
    acc.y += __shfl_xor_sync(0xffffffffu, acc.y, 16);
    acc.z += __shfl_xor_sync(0xffffffffu, acc.z, 16);
    acc.w += __shfl_xor_sync(0xffffffffu, acc.w, 16);

    if (half == 0) {
        float inv = 1.f / wsum;
        float4 b = reinterpret_cast<const float4*>(bias)[hl];
        out[(size_t)n * 16 + hl] = make_float4(acc.x * inv + b.x,
                                               acc.y * inv + b.y,
                                               acc.z * inv + b.z,
                                               acc.w * inv + b.w);
    }
}

// ---------------- launch ------------------------------------------------------
extern "C" void kernel_launch(void* const* d_in, const int* in_sizes, int n_in,
                              void* d_out, int out_size)
{
    const float* x    = (const float*)d_in[0];
    const void*  ei   = d_in[1];
    const float* W    = (const float*)d_in[2];
    const float* asrc = (const float*)d_in[3];
    const float* adst = (const float*)d_in[4];
    const float* bias = (const float*)d_in[5];
    float*       out  = (float*)d_out;

    int N = in_sizes[0] / IN_DIM;
    int E = in_sizes[1] / 2;
    int nTiles = (N + 1023) / 1024;

    k0_detect<<<1, 1>>>((const long long*)ei, N);
    k2a_hist<<<(E + 255) / 256, 256>>>(ei, E, N);
    kS1_tile_scan<<<nTiles, 1024>>>(N);
    k1_gemm<<<(N + 127) / 128, 256>>>(x, W, N);              // 4th: profiled
    kA_dots<<<(N + 255) / 256, 256>>>(asrc, adst, N);
    kS23_finalize<<<(N + 255) / 256, 256>>>(N, E, nTiles);
    k2c_place<<<(E + 255) / 256, 256>>>(ei, E, N);
    k5_gather<<<(N + 7) / 8, 256>>>((float4*)out, bias, N);
}

// round 16
// speedup vs baseline: 1.1147x; 1.1147x over previous
#include <cuda_runtime.h>
#include <cuda_fp16.h>
#include <cstring>

#define IN_DIM 128
#define OUT_DIM 64
#define N_MAX 100000
#define E_MAX 1600000
#define NEG_SLOPE 0.2f

// ---------------- scratch (static device globals: allocation-free) ----------
__device__ float  d_h[(size_t)N_MAX * OUT_DIM];    // transformed features (fp32)
__device__ __half d_hh[(size_t)N_MAX * OUT_DIM];   // fp16 copy for k5 gather
__device__ float  d_as[N_MAX];                     // h @ att_src
__device__ float  d_ad[N_MAX];                     // h @ att_dst
__device__ int    d_deg[N_MAX];                    // in-degree histogram
__device__ int    d_excl[N_MAX];                   // tile-local exclusive prefix
__device__ int    d_bsum[128];                     // per-tile totals
__device__ int    d_start[N_MAX + 1];              // CSR row offsets (by dst)
__device__ int    d_cursor[N_MAX];                 // placement cursors
__device__ int2   d_rec[E_MAX];                    // bucketed (src, w-as-bits)
__device__ int    d_is64;                          // edge_index dtype flag

__device__ __forceinline__ float lrelu(float v) {
    return v > 0.f ? v : NEG_SLOPE * v;
}

// bit reinterpret helpers (register moves only)
__device__ __forceinline__ unsigned h2_bits(__half2 h) {
    unsigned u; memcpy(&u, &h, 4); return u;
}
__device__ __forceinline__ __half2 bits_h2(unsigned u) {
    __half2 h; memcpy(&h, &u, 4); return h;
}

// ---------------- K0: detect edge_index element width ------------------------
__global__ void k0_detect(const long long* __restrict__ ei, int N)
{
    int ok64 = 1;
    for (int i = 0; i < 64; i++) {
        long long v = ei[i];
        if (v < 0 || v >= (long long)N) { ok64 = 0; break; }
    }
    d_is64 = ok64;
}

// ---------------- K2a: dst-degree histogram ----------------------------------
__global__ __launch_bounds__(256) void k2a_hist(
    const void* __restrict__ ei_raw, int E, int N)
{
    int i = blockIdx.x * blockDim.x + threadIdx.x;
    if (i >= E) return;
    int d;
    if (d_is64) {
        d = (int)((const long long*)ei_raw)[(size_t)E + i];
    } else {
        d = ((const int*)ei_raw)[(size_t)E + i];
    }
    if ((unsigned)d >= (unsigned)N) d = 0;
    atomicAdd(&d_deg[d], 1);
}

// ---------------- kS1: per-tile scan ------------------------------------------
__global__ __launch_bounds__(1024) void kS1_tile_scan(int N)
{
    __shared__ int sh[1024];
    int t = threadIdx.x;
    int gi = blockIdx.x * 1024 + t;
    int v = (gi < N) ? d_deg[gi] : 0;
    sh[t] = v;
    __syncthreads();
#pragma unroll
    for (int off = 1; off < 1024; off <<= 1) {
        int u = (t >= off) ? sh[t - off] : 0;
        __syncthreads();
        sh[t] += u;
        __syncthreads();
    }
    if (gi < N) d_excl[gi] = sh[t] - v;
    if (t == 1023) d_bsum[blockIdx.x] = sh[t];
}

// ---------------- K1: 8x8 register-tile GEMM (R13 form) + fp16 h store -------
__global__ __launch_bounds__(256) void k1_gemm(
    const float* __restrict__ x, const float* __restrict__ W,
    const float* __restrict__ att_src, const float* __restrict__ att_dst, int N)
{
    __shared__ float Wc[IN_DIM * OUT_DIM];   // 32 KB, [k][c] row-major

    int t = threadIdx.x;
    {
        const float4* Wg = reinterpret_cast<const float4*>(W);
        float4* Ws = reinterpret_cast<float4*>(Wc);
        for (int i = t; i < IN_DIM * OUT_DIM / 4; i += 256) Ws[i] = Wg[i];
    }
    __syncthreads();

    int cg = t & 7;
    int rg = t >> 3;
    int row0 = blockIdx.x * 256 + rg * 8;

    float4 acc[8][2];
#pragma unroll
    for (int r = 0; r < 8; r++) {
        acc[r][0] = make_float4(0.f, 0.f, 0.f, 0.f);
        acc[r][1] = make_float4(0.f, 0.f, 0.f, 0.f);
    }

    const float4* x4  = reinterpret_cast<const float4*>(x);
    const float4* Wc4 = reinterpret_cast<const float4*>(Wc);

    for (int kq = 0; kq < IN_DIM / 4; kq++) {
        float4 xr[8];
#pragma unroll
        for (int r = 0; r < 8; r++) {
            int gr = row0 + r;
            xr[r] = (gr < N) ? x4[(size_t)gr * 32 + kq]
                             : make_float4(0.f, 0.f, 0.f, 0.f);
        }
#pragma unroll
        for (int kk = 0; kk < 4; kk++) {
            int k = kq * 4 + kk;
            float4 w0 = Wc4[k * 16 + cg * 2];
            float4 w1 = Wc4[k * 16 + cg * 2 + 1];
#pragma unroll
            for (int r = 0; r < 8; r++) {
                float xv = (kk == 0) ? xr[r].x : (kk == 1) ? xr[r].y
                         : (kk == 2) ? xr[r].z : xr[r].w;
                acc[r][0].x = fmaf(xv, w0.x, acc[r][0].x);
                acc[r][0].y = fmaf(xv, w0.y, acc[r][0].y);
                acc[r][0].z = fmaf(xv, w0.z, acc[r][0].z);
                acc[r][0].w = fmaf(xv, w0.w, acc[r][0].w);
                acc[r][1].x = fmaf(xv, w1.x, acc[r][1].x);
                acc[r][1].y = fmaf(xv, w1.y, acc[r][1].y);
                acc[r][1].z = fmaf(xv, w1.z, acc[r][1].z);
                acc[r][1].w = fmaf(xv, w1.w, acc[r][1].w);
            }
        }
    }

    // store h (fp32 + fp16 copy)
    float4* h4 = reinterpret_cast<float4*>(d_h);
    uint4*  hh4 = reinterpret_cast<uint4*>(d_hh);
#pragma unroll
    for (int r = 0; r < 8; r++) {
        int gr = row0 + r;
        if (gr < N) {
            h4[(size_t)gr * 16 + cg * 2]     = acc[r][0];
            h4[(size_t)gr * 16 + cg * 2 + 1] = acc[r][1];
            uint4 packed;
            packed.x = h2_bits(__floats2half2_rn(acc[r][0].x, acc[r][0].y));
            packed.y = h2_bits(__floats2half2_rn(acc[r][0].z, acc[r][0].w));
            packed.z = h2_bits(__floats2half2_rn(acc[r][1].x, acc[r][1].y));
            packed.w = h2_bits(__floats2half2_rn(acc[r][1].z, acc[r][1].w));
            hh4[(size_t)gr * 8 + cg] = packed;   // 8 uint4 per 64-col row
        }
    }

    // attention dots over this thread's 8 cols, reduce across the 8 cg lanes
    float4 As0 = reinterpret_cast<const float4*>(att_src)[cg * 2];
    float4 As1 = reinterpret_cast<const float4*>(att_src)[cg * 2 + 1];
    float4 Ad0 = reinterpret_cast<const float4*>(att_dst)[cg * 2];
    float4 Ad1 = reinterpret_cast<const float4*>(att_dst)[cg * 2 + 1];
    float ps[8], pd[8];
#pragma unroll
    for (int r = 0; r < 8; r++) {
        ps[r] = acc[r][0].x*As0.x + acc[r][0].y*As0.y + acc[r][0].z*As0.z + acc[r][0].w*As0.w
              + acc[r][1].x*As1.x + acc[r][1].y*As1.y + acc[r][1].z*As1.z + acc[r][1].w*As1.w;
        pd[r] = acc[r][0].x*Ad0.x + acc[r][0].y*Ad0.y + acc[r][0].z*Ad0.z + acc[r][0].w*Ad0.w
              + acc[r][1].x*Ad1.x + acc[r][1].y*Ad1.y + acc[r][1].z*Ad1.z + acc[r][1].w*Ad1.w;
    }
#pragma unroll
    for (int o = 4; o; o >>= 1) {
#pragma unroll
        for (int r = 0; r < 8; r++) {
            ps[r] += __shfl_xor_sync(0xffffffffu, ps[r], o);
            pd[r] += __shfl_xor_sync(0xffffffffu, pd[r], o);
        }
    }
    if (cg == 0) {
#pragma unroll
        for (int r = 0; r < 8; r++) {
            int gr = row0 + r;
            if (gr < N) { d_as[gr] = ps[r]; d_ad[gr] = pd[r]; }
        }
    }
}

// ---------------- kS23: finalize offsets + zero histogram --------------------
__global__ __launch_bounds__(256) void kS23_finalize(int N, int E, int nTiles)
{
    __shared__ int sh[128];
    int t = threadIdx.x;
    if (t < 128) sh[t] = (t < nTiles) ? d_bsum[t] : 0;
    __syncthreads();
    if (t == 0) {
        int run = 0;
        for (int i = 0; i < nTiles; i++) {
            int v = sh[i];
            sh[i] = run;
            run += v;
        }
    }
    __syncthreads();

    int i = blockIdx.x * blockDim.x + t;
    if (i < N) {
        int s = d_excl[i] + sh[i >> 10];
        d_start[i]  = s;
        d_cursor[i] = s;
        d_deg[i]    = 0;
    }
    if (i == 0) d_start[N] = E;
}

// ---------------- K2c: decode + weight + place --------------------------------
__global__ __launch_bounds__(256) void k2c_place(
    const void* __restrict__ ei_raw, int E, int N)
{
    int i = blockIdx.x * blockDim.x + threadIdx.x;
    if (i >= E) return;
    int s, d;
    if (d_is64) {
        const long long* p = (const long long*)ei_raw;
        s = (int)p[i];
        d = (int)p[(size_t)E + i];
    } else {
        const int* p = (const int*)ei_raw;
        s = p[i];
        d = p[(size_t)E + i];
    }
    if ((unsigned)s >= (unsigned)N) s = 0;
    if ((unsigned)d >= (unsigned)N) d = 0;

    float w = __expf(lrelu(d_as[s] + d_ad[d]));
    int p = atomicAdd(&d_cursor[d], 1);
    d_rec[p] = make_int2(s, __float_as_int(w));
}

// ---------------- K5: gather-aggregate, half-warp, fp16 h rows ---------------
// Lanes 0-15 edge j, lanes 16-31 edge j+1; each lane loads uint2 (4 fp16 cols
// = 8B; 16 lanes cover the 128B row). Accumulation in fp32.
__global__ __launch_bounds__(256) void k5_gather(
    float4* __restrict__ out, const float* __restrict__ bias, int N)
{
    int t = threadIdx.x;
    int warp = t >> 5, lane = t & 31;
    int half = lane >> 4;
    int hl   = lane & 15;
    int n = blockIdx.x * 8 + warp;
    if (n >= N) return;

    const uint2*  hh2 = reinterpret_cast<const uint2*>(d_hh);
    const float4* h4  = reinterpret_cast<const float4*>(d_h);

    float wself = __expf(lrelu(d_as[n] + d_ad[n]));
    float4 hv = h4[(size_t)n * 16 + hl];      // self term from fp32 h
    float4 acc;
    float wsum;
    if (half == 0) {
        acc = make_float4(wself * hv.x, wself * hv.y, wself * hv.z, wself * hv.w);
        wsum = wself;
    } else {
        acc = make_float4(0.f, 0.f, 0.f, 0.f);
        wsum = 0.f;
    }

    int beg = d_start[n], end = d_start[n + 1];
    int j = beg;
    for (; j + 4 <= end; j += 4) {
        int2 rA = d_rec[j + half];
        int2 rB = d_rec[j + 2 + half];
        uint2 uA = hh2[(size_t)rA.x * 16 + hl];
        uint2 uB = hh2[(size_t)rB.x * 16 + hl];
        float wA = __int_as_float(rA.y);
        float wB = __int_as_float(rB.y);
        float2 a0 = __half22float2(bits_h2(uA.x));
        float2 a1 = __half22float2(bits_h2(uA.y));
        float2 b0 = __half22float2(bits_h2(uB.x));
        float2 b1 = __half22float2(bits_h2(uB.y));
        acc.x = fmaf(wA, a0.x, acc.x); acc.y = fmaf(wA, a0.y, acc.y);
        acc.z = fmaf(wA, a1.x, acc.z); acc.w = fmaf(wA, a1.y, acc.w);
        acc.x = fmaf(wB, b0.x, acc.x); acc.y = fmaf(wB, b0.y, acc.y);
        acc.z = fmaf(wB, b1.x, acc.z); acc.w = fmaf(wB, b1.y, acc.w);
        wsum += wA + wB;
    }
    if (j + 2 <= end) {
        int2 r = d_rec[j + half];
        uint2 u = hh2[(size_t)r.x * 16 + hl];
        float w = __int_as_float(r.y);
        float2 a0 = __half22float2(bits_h2(u.x));
        float2 a1 = __half22float2(bits_h2(u.y));
        acc.x = fmaf(w, a0.x, acc.x); acc.y = fmaf(w, a0.y, acc.y);
        acc.z = fmaf(w, a1.x, acc.z); acc.w = fmaf(w, a1.y, acc.w);
        wsum += w;
        j += 2;
    }
    if (j < end) {
        int2 r = d_rec[j];
        uint2 u = hh2[(size_t)r.x * 16 + hl];
        float w = (half == 0) ? __int_as_float(r.y) : 0.f;
        float2 a0 = __half22float2(bits_h2(u.x));
        float2 a1 = __half22float2(bits_h2(u.y));
        acc.x = fmaf(w, a0.x, acc.x); acc.y = fmaf(w, a0.y, acc.y);
        acc.z = fmaf(w, a1.x, acc.z); acc.w = fmaf(w, a1.y, acc.w);
        wsum += w;
    }

    wsum  += __shfl_xor_sync(0xffffffffu, wsum,  16);
    acc.x += __shfl_xor_sync(0xffffffffu, acc.x, 16);
    acc.y += __shfl_xor_sync(0xffffffffu, acc.y, 16);
    acc.z += __shfl_xor_sync(0xffffffffu, acc.z, 16);
    acc.w += __shfl_xor_sync(0xffffffffu, acc.w, 16);

    if (half == 0) {
        float inv = 1.f / wsum;
        float4 b = reinterpret_cast<const float4*>(bias)[hl];
        out[(size_t)n * 16 + hl] = make_float4(acc.x * inv + b.x,
                                               acc.y * inv + b.y,
                                               acc.z * inv + b.z,
                                               acc.w * inv + b.w);
    }
}

// ---------------- launch ------------------------------------------------------
extern "C" void kernel_launch(void* const* d_in, const int* in_sizes, int n_in,
                              void* d_out, int out_size)
{
    const float* x    = (const float*)d_in[0];
    const void*  ei   = d_in[1];
    const float* W    = (const float*)d_in[2];
    const float* asrc = (const float*)d_in[3];
    const float* adst = (const float*)d_in[4];
    const float* bias = (const float*)d_in[5];
    float*       out  = (float*)d_out;

    int N = in_sizes[0] / IN_DIM;
    int E = in_sizes[1] / 2;
    int nTiles = (N + 1023) / 1024;

    k0_detect<<<1, 1>>>((const long long*)ei, N);
    k2a_hist<<<(E + 255) / 256, 256>>>(ei, E, N);
    kS1_tile_scan<<<nTiles, 1024>>>(N);
    k1_gemm<<<(N + 255) / 256, 256>>>(x, W, asrc, adst, N);   // 4th: profiled
    kS23_finalize<<<(N + 255) / 256, 256>>>(N, E, nTiles);
    k2c_place<<<(E + 255) / 256, 256>>>(ei, E, N);
    k5_gather<<<(N + 7) / 8, 256>>>((float4*)out, bias, N);
}